// round 1
// baseline (speedup 1.0000x reference)
#include <cuda_runtime.h>
#include <cuda_bf16.h>
#include <math.h>
#include <stdint.h>

// Problem constants
#define NB 16
#define NT 2048
#define NC 384
#define NE 8
#define NDFF 1536
#define NTOK (NB*NT)          // 32768
#define CAP 8192              // N*TOP_K/E*CAP_F
#define CHUNK 128
#define NCHUNK (NTOK/CHUNK)   // 256

// -------- device scratch (static, allocation-free) --------
__device__ int   g_expert[NTOK];
__device__ float g_gate[NTOK];
__device__ int   g_hist[NCHUNK][NE];
__device__ int   g_base[NCHUNK][NE];
__device__ int   g_total[NE];                 // kept counts (<= CAP)
__device__ int   g_idx[NE*CAP];               // token id per expert slot
__device__ float g_gslot[NE*CAP];             // gate per expert slot
__device__ float g_H[(size_t)NE*CAP*NDFF];    // intermediate h = relu(x@w1+b1)^2

// ---------------- routing: one warp per token ----------------
__global__ void route_kernel(const float* __restrict__ x,
                             const float* __restrict__ noise,
                             const float* __restrict__ wr, const float* __restrict__ br,
                             const float* __restrict__ wn, const float* __restrict__ bn)
{
    int warp = (blockIdx.x * blockDim.x + threadIdx.x) >> 5;
    int lane = threadIdx.x & 31;
    if (warp >= NTOK) return;
    const float* xr = x + (size_t)warp * NC;

    float accr[NE], accn[NE];
#pragma unroll
    for (int e = 0; e < NE; e++) { accr[e] = 0.f; accn[e] = 0.f; }

    for (int c = lane; c < NC; c += 32) {
        float xv = xr[c];
#pragma unroll
        for (int e = 0; e < NE; e++) {
            accr[e] += xv * wr[c*NE + e];
            accn[e] += xv * wn[c*NE + e];
        }
    }
#pragma unroll
    for (int e = 0; e < NE; e++) {
#pragma unroll
        for (int o = 16; o > 0; o >>= 1) {
            accr[e] += __shfl_xor_sync(0xffffffffu, accr[e], o);
            accn[e] += __shfl_xor_sync(0xffffffffu, accn[e], o);
        }
    }
    if (lane == 0) {
        float v1 = -INFINITY, v2 = -INFINITY;
        int i1 = 0;
#pragma unroll
        for (int e = 0; e < NE; e++) {
            float z  = accn[e] + bn[e];
            float sp = (z > 20.f) ? z : log1pf(expf(z));     // softplus
            float nv = accr[e] + br[e] + noise[(size_t)warp*NE + e] * sp;
            if (nv > v1) { v2 = v1; v1 = nv; i1 = e; }
            else if (nv > v2) { v2 = nv; }
        }
        g_expert[warp] = i1;
        g_gate[warp]   = 1.f / (1.f + expf(v2 - v1));        // softmax over top-2
    }
}

// ---------------- dispatch: histogram / scan / scatter ----------------
__global__ void hist_kernel()
{
    __shared__ int h[NE];
    int tid = threadIdx.x;
    if (tid < NE) h[tid] = 0;
    __syncthreads();
    int t = blockIdx.x * CHUNK + tid;
    atomicAdd(&h[g_expert[t]], 1);
    __syncthreads();
    if (tid < NE) g_hist[blockIdx.x][tid] = h[tid];
}

__global__ void scan_kernel()
{
    int e = threadIdx.x;
    if (e >= NE) return;
    int running = 0;
    for (int ch = 0; ch < NCHUNK; ch++) {
        g_base[ch][e] = running;
        running += g_hist[ch][e];
    }
    g_total[e] = running < CAP ? running : CAP;
}

__global__ void scatter_kernel()
{
    __shared__ int se[CHUNK];
    int tid = threadIdx.x;
    int t = blockIdx.x * CHUNK + tid;
    se[tid] = g_expert[t];
    __syncthreads();
    int e = se[tid];
    int rank = 0;
    for (int j = 0; j < tid; j++) rank += (se[j] == e);
    int pos = g_base[blockIdx.x][e] + rank;
    if (pos < CAP) {
        g_idx[e*CAP + pos]   = t;
        g_gslot[e*CAP + pos] = g_gate[t];
    }
}

__global__ void zero_kernel(float4* __restrict__ out, int n4)
{
    int i = blockIdx.x * blockDim.x + threadIdx.x;
    if (i < n4) out[i] = make_float4(0.f, 0.f, 0.f, 0.f);
}

// ---------------- GEMM1: H = relu(X[idx] @ W1 + b1)^2 ----------------
// 64x64 tile, 256 threads, 4x4 microtile, K-tiles of 16
__global__ void ffn1_kernel(const float* __restrict__ x,
                            const float* __restrict__ w1,
                            const float* __restrict__ b1)
{
    int e = blockIdx.z;
    int rows = g_total[e];
    int row0 = blockIdx.x * 64;
    if (row0 >= rows) return;
    int col0 = blockIdx.y * 64;

    __shared__ float As[16][64];
    __shared__ float Bs[16][64];
    __shared__ int   stok[64];

    int tid = threadIdx.x;
    if (tid < 64) {
        int r = row0 + tid;
        stok[tid] = (r < rows) ? g_idx[e*CAP + r] : -1;
    }
    __syncthreads();

    const float* wptr = w1 + (size_t)e * NC * NDFF;
    int tx = tid & 15, ty = tid >> 4;

    float acc[4][4];
#pragma unroll
    for (int i = 0; i < 4; i++)
#pragma unroll
        for (int j = 0; j < 4; j++) acc[i][j] = 0.f;

    int lr = tid & 63;          // A load: row
    int lk = (tid >> 6) * 4;    // A load: k start
    int bk = tid >> 4;          // B load: k
    int bc = (tid & 15) * 4;    // B load: col start
    int tokA = stok[lr];

    for (int k0 = 0; k0 < NC; k0 += 16) {
        float4 av = (tokA >= 0)
            ? *reinterpret_cast<const float4*>(x + (size_t)tokA*NC + k0 + lk)
            : make_float4(0.f,0.f,0.f,0.f);
        As[lk+0][lr]=av.x; As[lk+1][lr]=av.y; As[lk+2][lr]=av.z; As[lk+3][lr]=av.w;
        *reinterpret_cast<float4*>(&Bs[bk][bc]) =
            *reinterpret_cast<const float4*>(wptr + (size_t)(k0+bk)*NDFF + col0 + bc);
        __syncthreads();
#pragma unroll
        for (int kk = 0; kk < 16; kk++) {
            float a[4], b[4];
#pragma unroll
            for (int i = 0; i < 4; i++) a[i] = As[kk][ty*4+i];
#pragma unroll
            for (int j = 0; j < 4; j++) b[j] = Bs[kk][tx*4+j];
#pragma unroll
            for (int i = 0; i < 4; i++)
#pragma unroll
                for (int j = 0; j < 4; j++) acc[i][j] += a[i]*b[j];
        }
        __syncthreads();
    }

    const float* bb = b1 + (size_t)e*NDFF + col0 + tx*4;
#pragma unroll
    for (int i = 0; i < 4; i++) {
        int r = row0 + ty*4 + i;
        if (r >= rows) continue;
        float* hp = g_H + ((size_t)e*CAP + r)*NDFF + col0 + tx*4;
#pragma unroll
        for (int j = 0; j < 4; j++) {
            float v = acc[i][j] + bb[j];
            v = fmaxf(v, 0.f);
            hp[j] = v * v;
        }
    }
}

// ---------------- GEMM2: out[tok] = (H @ W2 + b2) * gate ----------------
__global__ void ffn2_kernel(const float* __restrict__ w2,
                            const float* __restrict__ b2,
                            float* __restrict__ out)
{
    int e = blockIdx.z;
    int rows = g_total[e];
    int row0 = blockIdx.x * 64;
    if (row0 >= rows) return;
    int col0 = blockIdx.y * 64;

    __shared__ float As[16][64];
    __shared__ float Bs[16][64];
    __shared__ int   stok[64];
    __shared__ float sg[64];

    int tid = threadIdx.x;
    if (tid < 64) {
        int r = row0 + tid;
        stok[tid] = (r < rows) ? g_idx[e*CAP + r] : -1;
        sg[tid]   = (r < rows) ? g_gslot[e*CAP + r] : 0.f;
    }
    __syncthreads();

    const float* wptr = w2 + (size_t)e * NDFF * NC;
    const float* hbase = g_H + (size_t)e * CAP * NDFF;
    int tx = tid & 15, ty = tid >> 4;

    float acc[4][4];
#pragma unroll
    for (int i = 0; i < 4; i++)
#pragma unroll
        for (int j = 0; j < 4; j++) acc[i][j] = 0.f;

    int lr = tid & 63;
    int lk = (tid >> 6) * 4;
    int bk = tid >> 4;
    int bc = (tid & 15) * 4;

    for (int k0 = 0; k0 < NDFF; k0 += 16) {
        float4 av = *reinterpret_cast<const float4*>(
            hbase + (size_t)(row0 + lr)*NDFF + k0 + lk);
        As[lk+0][lr]=av.x; As[lk+1][lr]=av.y; As[lk+2][lr]=av.z; As[lk+3][lr]=av.w;
        *reinterpret_cast<float4*>(&Bs[bk][bc]) =
            *reinterpret_cast<const float4*>(wptr + (size_t)(k0+bk)*NC + col0 + bc);
        __syncthreads();
#pragma unroll
        for (int kk = 0; kk < 16; kk++) {
            float a[4], b[4];
#pragma unroll
            for (int i = 0; i < 4; i++) a[i] = As[kk][ty*4+i];
#pragma unroll
            for (int j = 0; j < 4; j++) b[j] = Bs[kk][tx*4+j];
#pragma unroll
            for (int i = 0; i < 4; i++)
#pragma unroll
                for (int j = 0; j < 4; j++) acc[i][j] += a[i]*b[j];
        }
        __syncthreads();
    }

    const float* bb = b2 + (size_t)e*NC + col0 + tx*4;
#pragma unroll
    for (int i = 0; i < 4; i++) {
        int rl = ty*4 + i;
        int r = row0 + rl;
        if (r >= rows) continue;
        int tok = stok[rl];
        float gte = sg[rl];
        float* op = out + (size_t)tok*NC + col0 + tx*4;
#pragma unroll
        for (int j = 0; j < 4; j++)
            op[j] = (acc[i][j] + bb[j]) * gte;
    }
}

// ---------------- launch ----------------
extern "C" void kernel_launch(void* const* d_in, const int* in_sizes, int n_in,
                              void* d_out, int out_size)
{
    const float* x  = (const float*)d_in[0];
    const float* noise = (const float*)d_in[1];
    const float* wr = (const float*)d_in[2];
    const float* br = (const float*)d_in[3];
    const float* wn = (const float*)d_in[4];
    const float* bn = (const float*)d_in[5];
    const float* w1 = (const float*)d_in[6];
    const float* b1 = (const float*)d_in[7];
    const float* w2 = (const float*)d_in[8];
    const float* b2 = (const float*)d_in[9];
    float* out = (float*)d_out;

    // 1. routing: 8 tokens per 256-thread block
    route_kernel<<<NTOK/8, 256>>>(x, noise, wr, br, wn, bn);

    // 2. capacity-ordered dispatch
    hist_kernel<<<NCHUNK, CHUNK>>>();
    scan_kernel<<<1, 32>>>();
    scatter_kernel<<<NCHUNK, CHUNK>>>();

    // 3. zero output (covers dropped tokens; out is poisoned)
    int n4 = out_size / 4;
    zero_kernel<<<(n4 + 255)/256, 256>>>((float4*)out, n4);

    // 4. expert FFN
    dim3 g1(CAP/64, NDFF/64, NE);
    ffn1_kernel<<<g1, 256>>>(x, w1, b1);
    dim3 g2(CAP/64, NC/64, NE);
    ffn2_kernel<<<g2, 256>>>(w2, b2, out);
}

// round 3
// speedup vs baseline: 2.4272x; 2.4272x over previous
#include <cuda_runtime.h>
#include <cuda_bf16.h>
#include <math.h>
#include <stdint.h>

// Problem constants
#define NB 16
#define NT 2048
#define NC 384
#define NE 8
#define NDFF 1536
#define NTOK (NB*NT)          // 32768
#define CAP 8192
#define CHUNK 128
#define NCHUNK (NTOK/CHUNK)   // 256

// ---------------- device scratch ----------------
__device__ int   g_expert[NTOK];
__device__ float g_gate[NTOK];
__device__ int   g_hist[NCHUNK][NE];
__device__ int   g_base[NCHUNK][NE];
__device__ int   g_total[NE];
__device__ int   g_idx[NE*CAP];
__device__ float g_gslot[NE*CAP];

__device__ __nv_bfloat16 g_xhi[(size_t)NTOK*NC];
__device__ __nv_bfloat16 g_xlo[(size_t)NTOK*NC];
__device__ __nv_bfloat16 g_w1hi[(size_t)NE*NDFF*NC];   // [E][DFF][C] K-major
__device__ __nv_bfloat16 g_w1lo[(size_t)NE*NDFF*NC];
__device__ __nv_bfloat16 g_w2hi[(size_t)NE*NC*NDFF];   // [E][C][DFF] K-major
__device__ __nv_bfloat16 g_w2lo[(size_t)NE*NC*NDFF];
__device__ __nv_bfloat16 g_Hhi[(size_t)NE*CAP*NDFF];
__device__ __nv_bfloat16 g_Hlo[(size_t)NE*CAP*NDFF];

// ---------------- helpers ----------------
__device__ __forceinline__ uint32_t smem_to_u32(const void* p) {
    uint32_t a;
    asm("{ .reg .u64 t; cvta.to.shared.u64 t, %1; cvt.u32.u64 %0, t; }" : "=r"(a) : "l"(p));
    return a;
}
__device__ __forceinline__ void ldsm4(uint32_t* r, uint32_t addr) {
    asm volatile("ldmatrix.sync.aligned.m8n8.x4.shared.b16 {%0,%1,%2,%3}, [%4];"
        : "=r"(r[0]), "=r"(r[1]), "=r"(r[2]), "=r"(r[3]) : "r"(addr));
}
__device__ __forceinline__ void mma16816(float* d, const uint32_t* a, const uint32_t* b) {
    asm volatile("mma.sync.aligned.m16n8k16.row.col.f32.bf16.bf16.f32 "
        "{%0,%1,%2,%3}, {%4,%5,%6,%7}, {%8,%9}, {%0,%1,%2,%3};"
        : "+f"(d[0]), "+f"(d[1]), "+f"(d[2]), "+f"(d[3])
        : "r"(a[0]), "r"(a[1]), "r"(a[2]), "r"(a[3]), "r"(b[0]), "r"(b[1]));
}
__device__ __forceinline__ void cp16(uint32_t dst, const void* src, int sz) {
    asm volatile("cp.async.cg.shared.global [%0], [%1], 16, %2;"
        :: "r"(dst), "l"(src), "r"(sz) : "memory");
}
#define CP_COMMIT() asm volatile("cp.async.commit_group;" ::: "memory")
#define CP_WAIT0()  asm volatile("cp.async.wait_group 0;" ::: "memory")

__device__ __forceinline__ void bf16split(float v, __nv_bfloat16& hi, __nv_bfloat16& lo) {
    hi = __float2bfloat16(v);
    lo = __float2bfloat16(v - __bfloat162float(hi));
}

// ---------------- routing ----------------
__global__ void route_kernel(const float* __restrict__ x,
                             const float* __restrict__ noise,
                             const float* __restrict__ wr, const float* __restrict__ br,
                             const float* __restrict__ wn, const float* __restrict__ bn)
{
    int warp = (blockIdx.x * blockDim.x + threadIdx.x) >> 5;
    int lane = threadIdx.x & 31;
    if (warp >= NTOK) return;
    const float* xr = x + (size_t)warp * NC;
    float accr[NE], accn[NE];
#pragma unroll
    for (int e = 0; e < NE; e++) { accr[e] = 0.f; accn[e] = 0.f; }
    for (int c = lane; c < NC; c += 32) {
        float xv = xr[c];
#pragma unroll
        for (int e = 0; e < NE; e++) {
            accr[e] += xv * wr[c*NE + e];
            accn[e] += xv * wn[c*NE + e];
        }
    }
#pragma unroll
    for (int e = 0; e < NE; e++) {
#pragma unroll
        for (int o = 16; o > 0; o >>= 1) {
            accr[e] += __shfl_xor_sync(0xffffffffu, accr[e], o);
            accn[e] += __shfl_xor_sync(0xffffffffu, accn[e], o);
        }
    }
    if (lane == 0) {
        float v1 = -INFINITY, v2 = -INFINITY;
        int i1 = 0;
#pragma unroll
        for (int e = 0; e < NE; e++) {
            float z  = accn[e] + bn[e];
            float sp = (z > 20.f) ? z : log1pf(expf(z));
            float nv = accr[e] + br[e] + noise[(size_t)warp*NE + e] * sp;
            if (nv > v1) { v2 = v1; v1 = nv; i1 = e; }
            else if (nv > v2) { v2 = nv; }
        }
        g_expert[warp] = i1;
        g_gate[warp]   = 1.f / (1.f + expf(v2 - v1));
    }
}

// ---------------- dispatch ----------------
__global__ void hist_kernel()
{
    __shared__ int h[NE];
    int tid = threadIdx.x;
    if (tid < NE) h[tid] = 0;
    __syncthreads();
    int t = blockIdx.x * CHUNK + tid;
    atomicAdd(&h[g_expert[t]], 1);
    __syncthreads();
    if (tid < NE) g_hist[blockIdx.x][tid] = h[tid];
}
__global__ void scan_kernel()
{
    int e = threadIdx.x;
    if (e >= NE) return;
    int running = 0;
    for (int ch = 0; ch < NCHUNK; ch++) {
        g_base[ch][e] = running;
        running += g_hist[ch][e];
    }
    g_total[e] = running < CAP ? running : CAP;
}
__global__ void scatter_kernel()
{
    __shared__ int se[CHUNK];
    int tid = threadIdx.x;
    int t = blockIdx.x * CHUNK + tid;
    se[tid] = g_expert[t];
    __syncthreads();
    int e = se[tid];
    int rank = 0;
    for (int j = 0; j < tid; j++) rank += (se[j] == e);
    int pos = g_base[blockIdx.x][e] + rank;
    if (pos < CAP) {
        g_idx[e*CAP + pos]   = t;
        g_gslot[e*CAP + pos] = g_gate[t];
    }
}
__global__ void zero_kernel(float4* __restrict__ out, int n4)
{
    int i = blockIdx.x * blockDim.x + threadIdx.x;
    if (i < n4) out[i] = make_float4(0.f, 0.f, 0.f, 0.f);
}

// ---------------- conversions ----------------
__global__ void cvt_x_kernel(const float* __restrict__ x)
{
    int i = (blockIdx.x * blockDim.x + threadIdx.x) * 4;
    float4 v = *(const float4*)(x + i);
    __nv_bfloat16 h0,l0,h1,l1,h2,l2,h3,l3;
    bf16split(v.x, h0, l0); bf16split(v.y, h1, l1);
    bf16split(v.z, h2, l2); bf16split(v.w, h3, l3);
    g_xhi[i+0]=h0; g_xhi[i+1]=h1; g_xhi[i+2]=h2; g_xhi[i+3]=h3;
    g_xlo[i+0]=l0; g_xlo[i+1]=l1; g_xlo[i+2]=l2; g_xlo[i+3]=l3;
}

// src [E][R][C] fp32 -> dst hi/lo [E][C][R] bf16
__global__ void transpose_cvt_kernel(const float* __restrict__ src,
                                     __nv_bfloat16* __restrict__ dhi,
                                     __nv_bfloat16* __restrict__ dlo,
                                     int R, int C)
{
    __shared__ float t[32][33];
    int e = blockIdx.z;
    const float* s = src + (size_t)e * R * C;
    size_t dbase = (size_t)e * R * C;
    int c0 = blockIdx.x * 32, r0 = blockIdx.y * 32;
    int tx = threadIdx.x, ty = threadIdx.y;   // 32 x 8
#pragma unroll
    for (int i = 0; i < 32; i += 8)
        t[ty + i][tx] = s[(size_t)(r0 + ty + i) * C + c0 + tx];
    __syncthreads();
#pragma unroll
    for (int i = 0; i < 32; i += 8) {
        float v = t[tx][ty + i];
        __nv_bfloat16 hi, lo; bf16split(v, hi, lo);
        size_t o = dbase + (size_t)(c0 + ty + i) * R + r0 + tx;
        dhi[o] = hi; dlo[o] = lo;
    }
}

// ================= bf16x3 mma FFN kernels =================
// Tile: 128(M) x 128(N), K-tile 32, 8 warps (2M x 4N), warp = 64x32.
// smem stage layout (bytes): AsHi 10240 | AsLo 10240 | BsHi 10240 | BsLo 10240
// rows padded to 40 bf16 (80B) -> conflict-free ldmatrix.
#define TSTRIDE 40
#define TILE_B  10240
#define STAGE_B (4*TILE_B)       // 40960
#define DYN_B   (2*STAGE_B)      // 81920

// GEMM1: A = gathered x (hi/lo), B = w1T (hi/lo), K=384. Out -> H hi/lo + bias/relu^2.
__global__ __launch_bounds__(256)
void ffn1_mma(const float* __restrict__ b1)
{
    int e = blockIdx.z;
    int rows = g_total[e];
    int row0 = blockIdx.x * 128;
    if (row0 >= rows) return;
    int n0 = blockIdx.y * 128;

    extern __shared__ char dyn[];
    uint32_t sbase = smem_to_u32(dyn);
    __shared__ int stok[128];

    int tid = threadIdx.x, lane = tid & 31, wid = tid >> 5;
    if (tid < 128) {
        int r = row0 + tid;
        stok[tid] = (r < rows) ? g_idx[e*CAP + r] : -1;
    }
    __syncthreads();

    const __nv_bfloat16* w1h = g_w1hi + (size_t)e * NDFF * NC;
    const __nv_bfloat16* w1l = g_w1lo + (size_t)e * NDFF * NC;

    // ---- stage loader: 2048 16B chunks (4 arrays x 128 rows x 4 segs) ----
    auto load_stage = [&](int kt, int stage) {
        int k0 = kt * 32;
        uint32_t sb = sbase + stage * STAGE_B;
#pragma unroll
        for (int i = 0; i < 8; i++) {
            int c = tid + i * 256;
            int arr = c >> 9, t = c & 511, row = t >> 2, seg = t & 3;
            uint32_t dst = sb + arr * TILE_B + (uint32_t)(row * TSTRIDE + seg * 8) * 2;
            if (arr < 2) {
                int tok = stok[row];
                const __nv_bfloat16* base = (arr == 0) ? g_xhi : g_xlo;
                const __nv_bfloat16* src = base + ((size_t)(tok < 0 ? 0 : tok) * NC + k0 + seg * 8);
                cp16(dst, src, (tok < 0) ? 0 : 16);
            } else {
                const __nv_bfloat16* base = (arr == 2) ? w1h : w1l;
                cp16(dst, base + ((size_t)(n0 + row) * NC + k0 + seg * 8), 16);
            }
        }
        CP_COMMIT();
    };

    int wm = wid >> 2, wn = wid & 3;
    float acc[4][4][4];
#pragma unroll
    for (int i = 0; i < 4; i++)
#pragma unroll
        for (int j = 0; j < 4; j++)
#pragma unroll
            for (int q = 0; q < 4; q++) acc[i][j][q] = 0.f;

    auto compute_stage = [&](int stage) {
        uint32_t aBase = sbase + stage * STAGE_B;
        uint32_t bBase = aBase + 2 * TILE_B;
#pragma unroll
        for (int ks = 0; ks < 32; ks += 16) {
            uint32_t ahi[4][4], alo[4][4], bhi[4][2], blo[4][2];
            uint32_t arow = (uint32_t)(wm * 64 + (lane & 15));
            uint32_t acol = (uint32_t)(ks + (lane >> 4) * 8);
#pragma unroll
            for (int i = 0; i < 4; i++) {
                uint32_t ad = aBase + ((arow + i * 16) * TSTRIDE + acol) * 2;
                ldsm4(ahi[i], ad);
                ldsm4(alo[i], ad + TILE_B);
            }
            uint32_t nloc = ((lane >> 4) & 1) * 8 + (lane & 7);
            uint32_t kof  = (uint32_t)(ks + ((lane >> 3) & 1) * 8);
#pragma unroll
            for (int jj = 0; jj < 2; jj++) {
                uint32_t bd = bBase + (((uint32_t)(wn * 32 + jj * 16) + nloc) * TSTRIDE + kof) * 2;
                uint32_t r[4];
                ldsm4(r, bd);
                bhi[jj*2][0]=r[0]; bhi[jj*2][1]=r[1]; bhi[jj*2+1][0]=r[2]; bhi[jj*2+1][1]=r[3];
                ldsm4(r, bd + TILE_B);
                blo[jj*2][0]=r[0]; blo[jj*2][1]=r[1]; blo[jj*2+1][0]=r[2]; blo[jj*2+1][1]=r[3];
            }
#pragma unroll
            for (int i = 0; i < 4; i++)
#pragma unroll
                for (int j = 0; j < 4; j++) {
                    mma16816(acc[i][j], ahi[i], bhi[j]);
                    mma16816(acc[i][j], alo[i], bhi[j]);
                    mma16816(acc[i][j], ahi[i], blo[j]);
                }
        }
    };

    load_stage(0, 0);
    for (int kt = 0; kt < 12; kt++) {
        CP_WAIT0();
        __syncthreads();
        if (kt + 1 < 12) load_stage(kt + 1, (kt + 1) & 1);
        compute_stage(kt & 1);
        __syncthreads();
    }

    // epilogue: +bias, relu^2, split to bf16 hi/lo -> g_H
    const float* b1e = b1 + (size_t)e * NDFF + n0;
    int r_in = lane >> 2, cpair = (lane & 3) * 2;
#pragma unroll
    for (int i = 0; i < 4; i++) {
        int r = row0 + wm * 64 + i * 16 + r_in;
#pragma unroll
        for (int j = 0; j < 4; j++) {
            int col = wn * 32 + j * 8 + cpair;
            float bb0 = b1e[col], bb1 = b1e[col + 1];
            float v00 = fmaxf(acc[i][j][0] + bb0, 0.f); v00 *= v00;
            float v01 = fmaxf(acc[i][j][1] + bb1, 0.f); v01 *= v01;
            float v10 = fmaxf(acc[i][j][2] + bb0, 0.f); v10 *= v10;
            float v11 = fmaxf(acc[i][j][3] + bb1, 0.f); v11 *= v11;
            __nv_bfloat16 h,l;
            size_t o0 = ((size_t)e*CAP + r) * NDFF + n0 + col;
            size_t o1 = o0 + (size_t)8 * NDFF;
            __nv_bfloat162 vh, vl;
            bf16split(v00, h, l); vh.x = h; vl.x = l;
            bf16split(v01, h, l); vh.y = h; vl.y = l;
            *(__nv_bfloat162*)(g_Hhi + o0) = vh;
            *(__nv_bfloat162*)(g_Hlo + o0) = vl;
            bf16split(v10, h, l); vh.x = h; vl.x = l;
            bf16split(v11, h, l); vh.y = h; vl.y = l;
            *(__nv_bfloat162*)(g_Hhi + o1) = vh;
            *(__nv_bfloat162*)(g_Hlo + o1) = vl;
        }
    }
}

// GEMM2: A = H (hi/lo), B = w2T (hi/lo), K=1536. Out -> scatter (acc+b2)*gate.
__global__ __launch_bounds__(256)
void ffn2_mma(const float* __restrict__ b2, float* __restrict__ out)
{
    int e = blockIdx.z;
    int rows = g_total[e];
    int row0 = blockIdx.x * 128;
    if (row0 >= rows) return;
    int n0 = blockIdx.y * 128;

    extern __shared__ char dyn[];
    uint32_t sbase = smem_to_u32(dyn);
    __shared__ int   stok[128];
    __shared__ float sg[128];

    int tid = threadIdx.x, lane = tid & 31, wid = tid >> 5;
    if (tid < 128) {
        int r = row0 + tid;
        stok[tid] = (r < rows) ? g_idx[e*CAP + r] : -1;
        sg[tid]   = (r < rows) ? g_gslot[e*CAP + r] : 0.f;
    }
    __syncthreads();

    const __nv_bfloat16* w2h = g_w2hi + (size_t)e * NC * NDFF;
    const __nv_bfloat16* w2l = g_w2lo + (size_t)e * NC * NDFF;
    const __nv_bfloat16* ahG = g_Hhi + (size_t)e * CAP * NDFF;
    const __nv_bfloat16* alG = g_Hlo + (size_t)e * CAP * NDFF;

    auto load_stage = [&](int kt, int stage) {
        int k0 = kt * 32;
        uint32_t sb = sbase + stage * STAGE_B;
#pragma unroll
        for (int i = 0; i < 8; i++) {
            int c = tid + i * 256;
            int arr = c >> 9, t = c & 511, row = t >> 2, seg = t & 3;
            uint32_t dst = sb + arr * TILE_B + (uint32_t)(row * TSTRIDE + seg * 8) * 2;
            if (arr < 2) {
                const __nv_bfloat16* base = (arr == 0) ? ahG : alG;
                cp16(dst, base + ((size_t)(row0 + row) * NDFF + k0 + seg * 8), 16);
            } else {
                const __nv_bfloat16* base = (arr == 2) ? w2h : w2l;
                cp16(dst, base + ((size_t)(n0 + row) * NDFF + k0 + seg * 8), 16);
            }
        }
        CP_COMMIT();
    };

    int wm = wid >> 2, wn = wid & 3;
    float acc[4][4][4];
#pragma unroll
    for (int i = 0; i < 4; i++)
#pragma unroll
        for (int j = 0; j < 4; j++)
#pragma unroll
            for (int q = 0; q < 4; q++) acc[i][j][q] = 0.f;

    auto compute_stage = [&](int stage) {
        uint32_t aBase = sbase + stage * STAGE_B;
        uint32_t bBase = aBase + 2 * TILE_B;
#pragma unroll
        for (int ks = 0; ks < 32; ks += 16) {
            uint32_t ahi[4][4], alo[4][4], bhi[4][2], blo[4][2];
            uint32_t arow = (uint32_t)(wm * 64 + (lane & 15));
            uint32_t acol = (uint32_t)(ks + (lane >> 4) * 8);
#pragma unroll
            for (int i = 0; i < 4; i++) {
                uint32_t ad = aBase + ((arow + i * 16) * TSTRIDE + acol) * 2;
                ldsm4(ahi[i], ad);
                ldsm4(alo[i], ad + TILE_B);
            }
            uint32_t nloc = ((lane >> 4) & 1) * 8 + (lane & 7);
            uint32_t kof  = (uint32_t)(ks + ((lane >> 3) & 1) * 8);
#pragma unroll
            for (int jj = 0; jj < 2; jj++) {
                uint32_t bd = bBase + (((uint32_t)(wn * 32 + jj * 16) + nloc) * TSTRIDE + kof) * 2;
                uint32_t r[4];
                ldsm4(r, bd);
                bhi[jj*2][0]=r[0]; bhi[jj*2][1]=r[1]; bhi[jj*2+1][0]=r[2]; bhi[jj*2+1][1]=r[3];
                ldsm4(r, bd + TILE_B);
                blo[jj*2][0]=r[0]; blo[jj*2][1]=r[1]; blo[jj*2+1][0]=r[2]; blo[jj*2+1][1]=r[3];
            }
#pragma unroll
            for (int i = 0; i < 4; i++)
#pragma unroll
                for (int j = 0; j < 4; j++) {
                    mma16816(acc[i][j], ahi[i], bhi[j]);
                    mma16816(acc[i][j], alo[i], bhi[j]);
                    mma16816(acc[i][j], ahi[i], blo[j]);
                }
        }
    };

    load_stage(0, 0);
    for (int kt = 0; kt < 48; kt++) {
        CP_WAIT0();
        __syncthreads();
        if (kt + 1 < 48) load_stage(kt + 1, (kt + 1) & 1);
        compute_stage(kt & 1);
        __syncthreads();
    }

    // epilogue: (acc + b2) * gate, scattered float2 stores
    const float* b2e = b2 + (size_t)e * NC + n0;
    int r_in = lane >> 2, cpair = (lane & 3) * 2;
#pragma unroll
    for (int i = 0; i < 4; i++) {
        int rl0 = wm * 64 + i * 16 + r_in;
        int rl1 = rl0 + 8;
#pragma unroll
        for (int j = 0; j < 4; j++) {
            int col = wn * 32 + j * 8 + cpair;
            float bb0 = b2e[col], bb1 = b2e[col + 1];
            if (row0 + rl0 < rows) {
                int tok = stok[rl0]; float g = sg[rl0];
                float2 v = make_float2((acc[i][j][0] + bb0) * g, (acc[i][j][1] + bb1) * g);
                *(float2*)(out + (size_t)tok * NC + n0 + col) = v;
            }
            if (row0 + rl1 < rows) {
                int tok = stok[rl1]; float g = sg[rl1];
                float2 v = make_float2((acc[i][j][2] + bb0) * g, (acc[i][j][3] + bb1) * g);
                *(float2*)(out + (size_t)tok * NC + n0 + col) = v;
            }
        }
    }
}

// ---------------- launch ----------------
extern "C" void kernel_launch(void* const* d_in, const int* in_sizes, int n_in,
                              void* d_out, int out_size)
{
    const float* x  = (const float*)d_in[0];
    const float* noise = (const float*)d_in[1];
    const float* wr = (const float*)d_in[2];
    const float* br = (const float*)d_in[3];
    const float* wn = (const float*)d_in[4];
    const float* bn = (const float*)d_in[5];
    const float* w1 = (const float*)d_in[6];
    const float* b1 = (const float*)d_in[7];
    const float* w2 = (const float*)d_in[8];
    const float* b2 = (const float*)d_in[9];
    float* out = (float*)d_out;

    cudaFuncSetAttribute(ffn1_mma, cudaFuncAttributeMaxDynamicSharedMemorySize, DYN_B);
    cudaFuncSetAttribute(ffn2_mma, cudaFuncAttributeMaxDynamicSharedMemorySize, DYN_B);

    // routing + dispatch
    route_kernel<<<NTOK/8, 256>>>(x, noise, wr, br, wn, bn);
    hist_kernel<<<NCHUNK, CHUNK>>>();
    scan_kernel<<<1, 32>>>();
    scatter_kernel<<<NCHUNK, CHUNK>>>();

    // zero output
    int n4 = out_size / 4;
    zero_kernel<<<(n4 + 255)/256, 256>>>((float4*)out, n4);

    // conversions
    cvt_x_kernel<<<(NTOK*NC/4 + 255)/256, 256>>>(x);
    {
        __nv_bfloat16 *w1h, *w1l, *w2h, *w2l;
        cudaGetSymbolAddress((void**)&w1h, g_w1hi);
        cudaGetSymbolAddress((void**)&w1l, g_w1lo);
        cudaGetSymbolAddress((void**)&w2h, g_w2hi);
        cudaGetSymbolAddress((void**)&w2l, g_w2lo);
        dim3 b(32, 8);
        transpose_cvt_kernel<<<dim3(NDFF/32, NC/32, NE), b>>>(w1, w1h, w1l, NC, NDFF);
        transpose_cvt_kernel<<<dim3(NC/32, NDFF/32, NE), b>>>(w2, w2h, w2l, NDFF, NC);
    }

    // FFN via bf16x3 mma
    dim3 g1(CAP/128, NDFF/128, NE);
    ffn1_mma<<<g1, 256, DYN_B>>>(b1);
    dim3 g2(CAP/128, NC/128, NE);
    ffn2_mma<<<g2, 256, DYN_B>>>(b2, out);
}

// round 5
// speedup vs baseline: 2.6689x; 1.0996x over previous
#include <cuda_runtime.h>
#include <cuda_bf16.h>
#include <math.h>
#include <stdint.h>

// Problem constants
#define NB 16
#define NT 2048
#define NC 384
#define NE 8
#define NDFF 1536
#define NTOK (NB*NT)          // 32768
#define CAP 8192
#define CHUNK 128
#define NCHUNK (NTOK/CHUNK)   // 256

// ---------------- device scratch ----------------
__device__ int   g_expert[NTOK];
__device__ float g_gate[NTOK];
__device__ int   g_hist[NCHUNK][NE];
__device__ int   g_base[NCHUNK][NE];
__device__ int   g_total[NE];
__device__ int   g_idx[NE*CAP];
__device__ float g_gslot[NE*CAP];

__device__ __nv_bfloat16 g_xhi[(size_t)NTOK*NC];
__device__ __nv_bfloat16 g_xlo[(size_t)NTOK*NC];
__device__ __nv_bfloat16 g_w1hi[(size_t)NE*NDFF*NC];   // [E][DFF][C] K-major
__device__ __nv_bfloat16 g_w1lo[(size_t)NE*NDFF*NC];
__device__ __nv_bfloat16 g_w2hi[(size_t)NE*NC*NDFF];   // [E][C][DFF] K-major
__device__ __nv_bfloat16 g_w2lo[(size_t)NE*NC*NDFF];
__device__ __nv_bfloat16 g_Hhi[(size_t)NE*CAP*NDFF];
__device__ __nv_bfloat16 g_Hlo[(size_t)NE*CAP*NDFF];

// ---------------- helpers ----------------
__device__ __forceinline__ uint32_t smem_to_u32(const void* p) {
    uint32_t a;
    asm("{ .reg .u64 t; cvta.to.shared.u64 t, %1; cvt.u32.u64 %0, t; }" : "=r"(a) : "l"(p));
    return a;
}
__device__ __forceinline__ void ldsm4(uint32_t* r, uint32_t addr) {
    asm volatile("ldmatrix.sync.aligned.m8n8.x4.shared.b16 {%0,%1,%2,%3}, [%4];"
        : "=r"(r[0]), "=r"(r[1]), "=r"(r[2]), "=r"(r[3]) : "r"(addr));
}
__device__ __forceinline__ void mma16816(float* d, const uint32_t* a, const uint32_t* b) {
    asm volatile("mma.sync.aligned.m16n8k16.row.col.f32.bf16.bf16.f32 "
        "{%0,%1,%2,%3}, {%4,%5,%6,%7}, {%8,%9}, {%0,%1,%2,%3};"
        : "+f"(d[0]), "+f"(d[1]), "+f"(d[2]), "+f"(d[3])
        : "r"(a[0]), "r"(a[1]), "r"(a[2]), "r"(a[3]), "r"(b[0]), "r"(b[1]));
}
__device__ __forceinline__ void cp16(uint32_t dst, const void* src, int sz) {
    asm volatile("cp.async.cg.shared.global [%0], [%1], 16, %2;"
        :: "r"(dst), "l"(src), "r"(sz) : "memory");
}
#define CP_COMMIT() asm volatile("cp.async.commit_group;" ::: "memory")
#define CP_WAIT0()  asm volatile("cp.async.wait_group 0;" ::: "memory")

__device__ __forceinline__ void bf16split(float v, __nv_bfloat16& hi, __nv_bfloat16& lo) {
    hi = __float2bfloat16(v);
    lo = __float2bfloat16(v - __bfloat162float(hi));
}

// ---------------- routing (+ x hi/lo split fused) ----------------
__global__ void route_kernel(const float* __restrict__ x,
                             const float* __restrict__ noise,
                             const float* __restrict__ wr, const float* __restrict__ br,
                             const float* __restrict__ wn, const float* __restrict__ bn)
{
    int warp = (blockIdx.x * blockDim.x + threadIdx.x) >> 5;
    int lane = threadIdx.x & 31;
    if (warp >= NTOK) return;
    const float* xr = x + (size_t)warp * NC;
    float accr[NE], accn[NE];
#pragma unroll
    for (int e = 0; e < NE; e++) { accr[e] = 0.f; accn[e] = 0.f; }
    for (int c = lane; c < NC; c += 32) {
        float xv = xr[c];
        __nv_bfloat16 hi, lo; bf16split(xv, hi, lo);
        g_xhi[(size_t)warp*NC + c] = hi;
        g_xlo[(size_t)warp*NC + c] = lo;
#pragma unroll
        for (int e = 0; e < NE; e++) {
            accr[e] += xv * wr[c*NE + e];
            accn[e] += xv * wn[c*NE + e];
        }
    }
#pragma unroll
    for (int e = 0; e < NE; e++) {
#pragma unroll
        for (int o = 16; o > 0; o >>= 1) {
            accr[e] += __shfl_xor_sync(0xffffffffu, accr[e], o);
            accn[e] += __shfl_xor_sync(0xffffffffu, accn[e], o);
        }
    }
    if (lane == 0) {
        float v1 = -INFINITY, v2 = -INFINITY;
        int i1 = 0;
#pragma unroll
        for (int e = 0; e < NE; e++) {
            float z  = accn[e] + bn[e];
            float sp = (z > 20.f) ? z : log1pf(expf(z));
            float nv = accr[e] + br[e] + noise[(size_t)warp*NE + e] * sp;
            if (nv > v1) { v2 = v1; v1 = nv; i1 = e; }
            else if (nv > v2) { v2 = nv; }
        }
        g_expert[warp] = i1;
        g_gate[warp]   = 1.f / (1.f + expf(v2 - v1));
    }
}

// ---------------- dispatch ----------------
__global__ void hist_kernel()
{
    __shared__ int h[NE];
    int tid = threadIdx.x;
    if (tid < NE) h[tid] = 0;
    __syncthreads();
    int t = blockIdx.x * CHUNK + tid;
    atomicAdd(&h[g_expert[t]], 1);
    __syncthreads();
    if (tid < NE) g_hist[blockIdx.x][tid] = h[tid];
}
__global__ void scan_kernel()
{
    int e = threadIdx.x;
    if (e >= NE) return;
    int running = 0;
    for (int ch = 0; ch < NCHUNK; ch++) {
        g_base[ch][e] = running;
        running += g_hist[ch][e];
    }
    g_total[e] = running < CAP ? running : CAP;
}
__global__ void scatter_kernel()
{
    __shared__ int se[CHUNK];
    int tid = threadIdx.x;
    int t = blockIdx.x * CHUNK + tid;
    se[tid] = g_expert[t];
    __syncthreads();
    int e = se[tid];
    int rank = 0;
    for (int j = 0; j < tid; j++) rank += (se[j] == e);
    int pos = g_base[blockIdx.x][e] + rank;
    if (pos < CAP) {
        g_idx[e*CAP + pos]   = t;
        g_gslot[e*CAP + pos] = g_gate[t];
    }
}
__global__ void zero_kernel(float4* __restrict__ out, int n4)
{
    int i = blockIdx.x * blockDim.x + threadIdx.x;
    if (i < n4) out[i] = make_float4(0.f, 0.f, 0.f, 0.f);
}

// ---------------- combined weight transpose+convert ----------------
// z<8 : w1 expert z   : [NC][NDFF] -> [NDFF][NC] hi/lo
// z>=8: w2 expert z-8 : [NDFF][NC] -> [NC][NDFF] hi/lo
__global__ void transpose_cvt_all(const float* __restrict__ w1,
                                  const float* __restrict__ w2)
{
    __shared__ float t[32][33];
    int z = blockIdx.z;
    int R, C, c_blk, r_blk;
    const float* s;
    __nv_bfloat16 *dhi, *dlo;
    if (z < NE) {
        R = NC; C = NDFF;
        s = w1 + (size_t)z * R * C;
        dhi = g_w1hi + (size_t)z * R * C;
        dlo = g_w1lo + (size_t)z * R * C;
        c_blk = blockIdx.x; r_blk = blockIdx.y;    // x: 48, y: 12
    } else {
        R = NDFF; C = NC;
        s = w2 + (size_t)(z - NE) * R * C;
        dhi = g_w2hi + (size_t)(z - NE) * R * C;
        dlo = g_w2lo + (size_t)(z - NE) * R * C;
        r_blk = blockIdx.x; c_blk = blockIdx.y;    // x: 48 = R/32, y: 12 = C/32
    }
    int c0 = c_blk * 32, r0 = r_blk * 32;
    int tx = threadIdx.x, ty = threadIdx.y;        // 32 x 8
#pragma unroll
    for (int i = 0; i < 32; i += 8)
        t[ty + i][tx] = s[(size_t)(r0 + ty + i) * C + c0 + tx];
    __syncthreads();
#pragma unroll
    for (int i = 0; i < 32; i += 8) {
        float v = t[tx][ty + i];
        __nv_bfloat16 hi, lo; bf16split(v, hi, lo);
        size_t o = (size_t)(c0 + ty + i) * R + r0 + tx;
        dhi[o] = hi; dlo[o] = lo;
    }
}

// ================= bf16x3 mma FFN kernels =================
#define TSTRIDE 40
#define TILE_B  10240
#define STAGE_B (4*TILE_B)       // 40960
#define DYN_B   (2*STAGE_B)      // 81920

// GEMM1: A = gathered x (hi/lo), B = w1T (hi/lo), K=384. Out -> H hi/lo + bias/relu^2.
__global__ __launch_bounds__(256, 2)
void ffn1_mma(const float* __restrict__ b1)
{
    int e = blockIdx.z;
    int rows = g_total[e];
    int row0 = blockIdx.x * 128;
    if (row0 >= rows) return;
    int n0 = blockIdx.y * 128;

    extern __shared__ char dyn[];
    uint32_t sbase = smem_to_u32(dyn);
    __shared__ int stok[128];

    int tid = threadIdx.x, lane = tid & 31, wid = tid >> 5;
    if (tid < 128) {
        int r = row0 + tid;
        stok[tid] = (r < rows) ? g_idx[e*CAP + r] : -1;
    }
    __syncthreads();

    const __nv_bfloat16* w1h = g_w1hi + (size_t)e * NDFF * NC;
    const __nv_bfloat16* w1l = g_w1lo + (size_t)e * NDFF * NC;

    auto load_stage = [&](int kt, int stage) {
        int k0 = kt * 32;
        uint32_t sb = sbase + stage * STAGE_B;
#pragma unroll
        for (int i = 0; i < 8; i++) {
            int c = tid + i * 256;
            int arr = c >> 9, t = c & 511, row = t >> 2, seg = t & 3;
            uint32_t dst = sb + arr * TILE_B + (uint32_t)(row * TSTRIDE + seg * 8) * 2;
            if (arr < 2) {
                int tok = stok[row];
                const __nv_bfloat16* base = (arr == 0) ? g_xhi : g_xlo;
                const __nv_bfloat16* src = base + ((size_t)(tok < 0 ? 0 : tok) * NC + k0 + seg * 8);
                cp16(dst, src, (tok < 0) ? 0 : 16);
            } else {
                const __nv_bfloat16* base = (arr == 2) ? w1h : w1l;
                cp16(dst, base + ((size_t)(n0 + row) * NC + k0 + seg * 8), 16);
            }
        }
        CP_COMMIT();
    };

    int wm = wid >> 2, wn = wid & 3;
    float acc[4][4][4];
#pragma unroll
    for (int i = 0; i < 4; i++)
#pragma unroll
        for (int j = 0; j < 4; j++)
#pragma unroll
            for (int q = 0; q < 4; q++) acc[i][j][q] = 0.f;

    auto compute_stage = [&](int stage) {
        uint32_t aBase = sbase + stage * STAGE_B;
        uint32_t bBase = aBase + 2 * TILE_B;
#pragma unroll
        for (int ks = 0; ks < 32; ks += 16) {
            uint32_t bhi[4][2], blo[4][2];
            uint32_t nloc = ((lane >> 4) & 1) * 8 + (lane & 7);
            uint32_t kof  = (uint32_t)(ks + ((lane >> 3) & 1) * 8);
#pragma unroll
            for (int jj = 0; jj < 2; jj++) {
                uint32_t bd = bBase + (((uint32_t)(wn * 32 + jj * 16) + nloc) * TSTRIDE + kof) * 2;
                uint32_t r[4];
                ldsm4(r, bd);
                bhi[jj*2][0]=r[0]; bhi[jj*2][1]=r[1]; bhi[jj*2+1][0]=r[2]; bhi[jj*2+1][1]=r[3];
                ldsm4(r, bd + TILE_B);
                blo[jj*2][0]=r[0]; blo[jj*2][1]=r[1]; blo[jj*2+1][0]=r[2]; blo[jj*2+1][1]=r[3];
            }
            uint32_t arow = (uint32_t)(wm * 64 + (lane & 15));
            uint32_t acol = (uint32_t)(ks + (lane >> 4) * 8);
#pragma unroll
            for (int i = 0; i < 4; i++) {
                uint32_t ah[4], al[4];
                uint32_t ad = aBase + ((arow + i * 16) * TSTRIDE + acol) * 2;
                ldsm4(ah, ad);
                ldsm4(al, ad + TILE_B);
#pragma unroll
                for (int j = 0; j < 4; j++) {
                    mma16816(acc[i][j], ah, bhi[j]);
                    mma16816(acc[i][j], al, bhi[j]);
                    mma16816(acc[i][j], ah, blo[j]);
                }
            }
        }
    };

    load_stage(0, 0);
    for (int kt = 0; kt < 12; kt++) {
        CP_WAIT0();
        __syncthreads();
        if (kt + 1 < 12) load_stage(kt + 1, (kt + 1) & 1);
        compute_stage(kt & 1);
        __syncthreads();
    }

    // epilogue: +bias, relu^2, split to bf16 hi/lo -> g_H
    const float* b1e = b1 + (size_t)e * NDFF + n0;
    int r_in = lane >> 2, cpair = (lane & 3) * 2;
#pragma unroll
    for (int i = 0; i < 4; i++) {
        int r = row0 + wm * 64 + i * 16 + r_in;
#pragma unroll
        for (int j = 0; j < 4; j++) {
            int col = wn * 32 + j * 8 + cpair;
            float bb0 = b1e[col], bb1 = b1e[col + 1];
            float v00 = fmaxf(acc[i][j][0] + bb0, 0.f); v00 *= v00;
            float v01 = fmaxf(acc[i][j][1] + bb1, 0.f); v01 *= v01;
            float v10 = fmaxf(acc[i][j][2] + bb0, 0.f); v10 *= v10;
            float v11 = fmaxf(acc[i][j][3] + bb1, 0.f); v11 *= v11;
            __nv_bfloat16 h,l;
            size_t o0 = ((size_t)e*CAP + r) * NDFF + n0 + col;
            size_t o1 = o0 + (size_t)8 * NDFF;
            __nv_bfloat162 vh, vl;
            bf16split(v00, h, l); vh.x = h; vl.x = l;
            bf16split(v01, h, l); vh.y = h; vl.y = l;
            *(__nv_bfloat162*)(g_Hhi + o0) = vh;
            *(__nv_bfloat162*)(g_Hlo + o0) = vl;
            bf16split(v10, h, l); vh.x = h; vl.x = l;
            bf16split(v11, h, l); vh.y = h; vl.y = l;
            *(__nv_bfloat162*)(g_Hhi + o1) = vh;
            *(__nv_bfloat162*)(g_Hlo + o1) = vl;
        }
    }
}

// GEMM2: A = H (hi/lo), B = w2T (hi/lo), K=1536. Out -> scatter (acc+b2)*gate.
__global__ __launch_bounds__(256, 2)
void ffn2_mma(const float* __restrict__ b2, float* __restrict__ out)
{
    int e = blockIdx.z;
    int rows = g_total[e];
    int row0 = blockIdx.x * 128;
    if (row0 >= rows) return;
    int n0 = blockIdx.y * 128;

    extern __shared__ char dyn[];
    uint32_t sbase = smem_to_u32(dyn);
    __shared__ int   stok[128];
    __shared__ float sg[128];

    int tid = threadIdx.x, lane = tid & 31, wid = tid >> 5;
    if (tid < 128) {
        int r = row0 + tid;
        stok[tid] = (r < rows) ? g_idx[e*CAP + r] : -1;
        sg[tid]   = (r < rows) ? g_gslot[e*CAP + r] : 0.f;
    }
    __syncthreads();

    const __nv_bfloat16* w2h = g_w2hi + (size_t)e * NC * NDFF;
    const __nv_bfloat16* w2l = g_w2lo + (size_t)e * NC * NDFF;
    const __nv_bfloat16* ahG = g_Hhi + (size_t)e * CAP * NDFF;
    const __nv_bfloat16* alG = g_Hlo + (size_t)e * CAP * NDFF;

    auto load_stage = [&](int kt, int stage) {
        int k0 = kt * 32;
        uint32_t sb = sbase + stage * STAGE_B;
#pragma unroll
        for (int i = 0; i < 8; i++) {
            int c = tid + i * 256;
            int arr = c >> 9, t = c & 511, row = t >> 2, seg = t & 3;
            uint32_t dst = sb + arr * TILE_B + (uint32_t)(row * TSTRIDE + seg * 8) * 2;
            if (arr < 2) {
                const __nv_bfloat16* base = (arr == 0) ? ahG : alG;
                cp16(dst, base + ((size_t)(row0 + row) * NDFF + k0 + seg * 8), 16);
            } else {
                const __nv_bfloat16* base = (arr == 2) ? w2h : w2l;
                cp16(dst, base + ((size_t)(n0 + row) * NDFF + k0 + seg * 8), 16);
            }
        }
        CP_COMMIT();
    };

    int wm = wid >> 2, wn = wid & 3;
    float acc[4][4][4];
#pragma unroll
    for (int i = 0; i < 4; i++)
#pragma unroll
        for (int j = 0; j < 4; j++)
#pragma unroll
            for (int q = 0; q < 4; q++) acc[i][j][q] = 0.f;

    auto compute_stage = [&](int stage) {
        uint32_t aBase = sbase + stage * STAGE_B;
        uint32_t bBase = aBase + 2 * TILE_B;
#pragma unroll
        for (int ks = 0; ks < 32; ks += 16) {
            uint32_t bhi[4][2], blo[4][2];
            uint32_t nloc = ((lane >> 4) & 1) * 8 + (lane & 7);
            uint32_t kof  = (uint32_t)(ks + ((lane >> 3) & 1) * 8);
#pragma unroll
            for (int jj = 0; jj < 2; jj++) {
                uint32_t bd = bBase + (((uint32_t)(wn * 32 + jj * 16) + nloc) * TSTRIDE + kof) * 2;
                uint32_t r[4];
                ldsm4(r, bd);
                bhi[jj*2][0]=r[0]; bhi[jj*2][1]=r[1]; bhi[jj*2+1][0]=r[2]; bhi[jj*2+1][1]=r[3];
                ldsm4(r, bd + TILE_B);
                blo[jj*2][0]=r[0]; blo[jj*2][1]=r[1]; blo[jj*2+1][0]=r[2]; blo[jj*2+1][1]=r[3];
            }
            uint32_t arow = (uint32_t)(wm * 64 + (lane & 15));
            uint32_t acol = (uint32_t)(ks + (lane >> 4) * 8);
#pragma unroll
            for (int i = 0; i < 4; i++) {
                uint32_t ah[4], al[4];
                uint32_t ad = aBase + ((arow + i * 16) * TSTRIDE + acol) * 2;
                ldsm4(ah, ad);
                ldsm4(al, ad + TILE_B);
#pragma unroll
                for (int j = 0; j < 4; j++) {
                    mma16816(acc[i][j], ah, bhi[j]);
                    mma16816(acc[i][j], al, bhi[j]);
                    mma16816(acc[i][j], ah, blo[j]);
                }
            }
        }
    };

    load_stage(0, 0);
    for (int kt = 0; kt < 48; kt++) {
        CP_WAIT0();
        __syncthreads();
        if (kt + 1 < 48) load_stage(kt + 1, (kt + 1) & 1);
        compute_stage(kt & 1);
        __syncthreads();
    }

    // epilogue: (acc + b2) * gate, scattered float2 stores
    const float* b2e = b2 + (size_t)e * NC + n0;
    int r_in = lane >> 2, cpair = (lane & 3) * 2;
#pragma unroll
    for (int i = 0; i < 4; i++) {
        int rl0 = wm * 64 + i * 16 + r_in;
        int rl1 = rl0 + 8;
#pragma unroll
        for (int j = 0; j < 4; j++) {
            int col = wn * 32 + j * 8 + cpair;
            float bb0 = b2e[col], bb1 = b2e[col + 1];
            if (row0 + rl0 < rows) {
                int tok = stok[rl0]; float g = sg[rl0];
                float2 v = make_float2((acc[i][j][0] + bb0) * g, (acc[i][j][1] + bb1) * g);
                *(float2*)(out + (size_t)tok * NC + n0 + col) = v;
            }
            if (row0 + rl1 < rows) {
                int tok = stok[rl1]; float g = sg[rl1];
                float2 v = make_float2((acc[i][j][2] + bb0) * g, (acc[i][j][3] + bb1) * g);
                *(float2*)(out + (size_t)tok * NC + n0 + col) = v;
            }
        }
    }
}

// ---------------- launch ----------------
extern "C" void kernel_launch(void* const* d_in, const int* in_sizes, int n_in,
                              void* d_out, int out_size)
{
    const float* x  = (const float*)d_in[0];
    const float* noise = (const float*)d_in[1];
    const float* wr = (const float*)d_in[2];
    const float* br = (const float*)d_in[3];
    const float* wn = (const float*)d_in[4];
    const float* bn = (const float*)d_in[5];
    const float* w1 = (const float*)d_in[6];
    const float* b1 = (const float*)d_in[7];
    const float* w2 = (const float*)d_in[8];
    const float* b2 = (const float*)d_in[9];
    float* out = (float*)d_out;

    cudaFuncSetAttribute(ffn1_mma, cudaFuncAttributeMaxDynamicSharedMemorySize, DYN_B);
    cudaFuncSetAttribute(ffn2_mma, cudaFuncAttributeMaxDynamicSharedMemorySize, DYN_B);

    // 1-4: routing + dispatch (x split fused into route)
    route_kernel<<<NTOK/8, 256>>>(x, noise, wr, br, wn, bn);
    hist_kernel<<<NCHUNK, CHUNK>>>();
    scan_kernel<<<1, 32>>>();
    scatter_kernel<<<NCHUNK, CHUNK>>>();

    // 5: weight transpose+convert (both weights, one kernel)
    transpose_cvt_all<<<dim3(48, 12, 2*NE), dim3(32, 8)>>>(w1, w2);

    // 6: GEMM1  (profiled slot: ncu -s 5 -c 1)
    dim3 g1(CAP/128, NDFF/128, NE);
    ffn1_mma<<<g1, 256, DYN_B>>>(b1);

    // 7: zero output (only needs to precede ffn2)
    int n4 = out_size / 4;
    zero_kernel<<<(n4 + 255)/256, 256>>>((float4*)out, n4);

    // 8: GEMM2
    dim3 g2(CAP/128, NC/128, NE);
    ffn2_mma<<<g2, 256, DYN_B>>>(b2, out);
}

// round 6
// speedup vs baseline: 4.5959x; 1.7220x over previous
#include <cuda_runtime.h>
#include <cuda_fp16.h>
#include <math.h>
#include <stdint.h>

// Problem constants
#define NB 16
#define NT 2048
#define NC 384
#define NE 8
#define NDFF 1536
#define NTOK (NB*NT)          // 32768
#define CAP 8192
#define CHUNK 128
#define NCHUNK (NTOK/CHUNK)   // 256

// ---------------- device scratch ----------------
__device__ int   g_expert[NTOK];
__device__ float g_gate[NTOK];
__device__ int   g_hist[NCHUNK][NE];
__device__ int   g_base[NCHUNK][NE];
__device__ int   g_total[NE];
__device__ int   g_idx[NE*CAP];
__device__ float g_gslot[NE*CAP];

__device__ __half g_xh[(size_t)NTOK*NC];
__device__ __half g_w1h[(size_t)NE*NDFF*NC];   // [E][DFF][C] K-major
__device__ __half g_w2h[(size_t)NE*NC*NDFF];   // [E][C][DFF] K-major
__device__ __half g_Hh[(size_t)NE*CAP*NDFF];

// ---------------- helpers ----------------
__device__ __forceinline__ uint32_t smem_to_u32(const void* p) {
    uint32_t a;
    asm("{ .reg .u64 t; cvta.to.shared.u64 t, %1; cvt.u32.u64 %0, t; }" : "=r"(a) : "l"(p));
    return a;
}
__device__ __forceinline__ void ldsm4(uint32_t* r, uint32_t addr) {
    asm volatile("ldmatrix.sync.aligned.m8n8.x4.shared.b16 {%0,%1,%2,%3}, [%4];"
        : "=r"(r[0]), "=r"(r[1]), "=r"(r[2]), "=r"(r[3]) : "r"(addr));
}
__device__ __forceinline__ void mma16816(float* d, const uint32_t* a, const uint32_t* b) {
    asm volatile("mma.sync.aligned.m16n8k16.row.col.f32.f16.f16.f32 "
        "{%0,%1,%2,%3}, {%4,%5,%6,%7}, {%8,%9}, {%0,%1,%2,%3};"
        : "+f"(d[0]), "+f"(d[1]), "+f"(d[2]), "+f"(d[3])
        : "r"(a[0]), "r"(a[1]), "r"(a[2]), "r"(a[3]), "r"(b[0]), "r"(b[1]));
}
__device__ __forceinline__ void cp16(uint32_t dst, const void* src, int sz) {
    asm volatile("cp.async.cg.shared.global [%0], [%1], 16, %2;"
        :: "r"(dst), "l"(src), "r"(sz) : "memory");
}
#define CP_COMMIT() asm volatile("cp.async.commit_group;" ::: "memory")
#define CP_WAIT0()  asm volatile("cp.async.wait_group 0;" ::: "memory")

// ---------------- routing (+ x fp16 convert fused) ----------------
__global__ void route_kernel(const float* __restrict__ x,
                             const float* __restrict__ noise,
                             const float* __restrict__ wr, const float* __restrict__ br,
                             const float* __restrict__ wn, const float* __restrict__ bn)
{
    int warp = (blockIdx.x * blockDim.x + threadIdx.x) >> 5;
    int lane = threadIdx.x & 31;
    if (warp >= NTOK) return;
    const float* xr = x + (size_t)warp * NC;
    float accr[NE], accn[NE];
#pragma unroll
    for (int e = 0; e < NE; e++) { accr[e] = 0.f; accn[e] = 0.f; }
    for (int c = lane; c < NC; c += 32) {
        float xv = xr[c];
        g_xh[(size_t)warp*NC + c] = __float2half_rn(xv);
#pragma unroll
        for (int e = 0; e < NE; e++) {
            accr[e] += xv * wr[c*NE + e];
            accn[e] += xv * wn[c*NE + e];
        }
    }
#pragma unroll
    for (int e = 0; e < NE; e++) {
#pragma unroll
        for (int o = 16; o > 0; o >>= 1) {
            accr[e] += __shfl_xor_sync(0xffffffffu, accr[e], o);
            accn[e] += __shfl_xor_sync(0xffffffffu, accn[e], o);
        }
    }
    if (lane == 0) {
        float v1 = -INFINITY, v2 = -INFINITY;
        int i1 = 0;
#pragma unroll
        for (int e = 0; e < NE; e++) {
            float z  = accn[e] + bn[e];
            float sp = (z > 20.f) ? z : log1pf(expf(z));
            float nv = accr[e] + br[e] + noise[(size_t)warp*NE + e] * sp;
            if (nv > v1) { v2 = v1; v1 = nv; i1 = e; }
            else if (nv > v2) { v2 = nv; }
        }
        g_expert[warp] = i1;
        g_gate[warp]   = 1.f / (1.f + expf(v2 - v1));
    }
}

// ---------------- dispatch ----------------
__global__ void hist_kernel()
{
    __shared__ int h[NE];
    int tid = threadIdx.x;
    if (tid < NE) h[tid] = 0;
    __syncthreads();
    int t = blockIdx.x * CHUNK + tid;
    atomicAdd(&h[g_expert[t]], 1);
    __syncthreads();
    if (tid < NE) g_hist[blockIdx.x][tid] = h[tid];
}
__global__ void scan_kernel()
{
    int e = threadIdx.x;
    if (e >= NE) return;
    int running = 0;
    for (int ch = 0; ch < NCHUNK; ch++) {
        g_base[ch][e] = running;
        running += g_hist[ch][e];
    }
    g_total[e] = running < CAP ? running : CAP;
}
__global__ void scatter_kernel()
{
    __shared__ int se[CHUNK];
    int tid = threadIdx.x;
    int t = blockIdx.x * CHUNK + tid;
    se[tid] = g_expert[t];
    __syncthreads();
    int e = se[tid];
    int rank = 0;
    for (int j = 0; j < tid; j++) rank += (se[j] == e);
    int pos = g_base[blockIdx.x][e] + rank;
    if (pos < CAP) {
        g_idx[e*CAP + pos]   = t;
        g_gslot[e*CAP + pos] = g_gate[t];
    }
}
__global__ void zero_kernel(float4* __restrict__ out, int n4)
{
    int i = blockIdx.x * blockDim.x + threadIdx.x;
    if (i < n4) out[i] = make_float4(0.f, 0.f, 0.f, 0.f);
}

// ---------------- combined weight transpose+convert (fp16) ----------------
// z<8 : w1 expert z   : [NC][NDFF] -> [NDFF][NC]
// z>=8: w2 expert z-8 : [NDFF][NC] -> [NC][NDFF]
__global__ void transpose_cvt_all(const float* __restrict__ w1,
                                  const float* __restrict__ w2)
{
    __shared__ float t[32][33];
    int z = blockIdx.z;
    int R, C, c_blk, r_blk;
    const float* s;
    __half* dh;
    if (z < NE) {
        R = NC; C = NDFF;
        s = w1 + (size_t)z * R * C;
        dh = g_w1h + (size_t)z * R * C;
        c_blk = blockIdx.x; r_blk = blockIdx.y;    // x: 48, y: 12
    } else {
        R = NDFF; C = NC;
        s = w2 + (size_t)(z - NE) * R * C;
        dh = g_w2h + (size_t)(z - NE) * R * C;
        r_blk = blockIdx.x; c_blk = blockIdx.y;    // x: 48 = R/32, y: 12 = C/32
    }
    int c0 = c_blk * 32, r0 = r_blk * 32;
    int tx = threadIdx.x, ty = threadIdx.y;        // 32 x 8
#pragma unroll
    for (int i = 0; i < 32; i += 8)
        t[ty + i][tx] = s[(size_t)(r0 + ty + i) * C + c0 + tx];
    __syncthreads();
#pragma unroll
    for (int i = 0; i < 32; i += 8) {
        float v = t[tx][ty + i];
        dh[(size_t)(c0 + ty + i) * R + r0 + tx] = __float2half_rn(v);
    }
}

// ================= fp16 mma FFN kernels =================
// Tile 128(M) x 128(N), K-tile 32, 8 warps (2M x 4N), warp = 64x32.
// smem rows padded to 40 halves (80B) -> conflict-free ldmatrix.
#define TSTRIDE 40
#define TILE_B  10240
#define STAGE_B (2*TILE_B)       // 20480 (A + B)
#define DYN_B   (2*STAGE_B)      // 40960 double-buffered

// GEMM1: A = gathered x, B = w1T, K=384. Out -> H (fp16) after bias/relu^2.
__global__ __launch_bounds__(256, 2)
void ffn1_mma(const float* __restrict__ b1)
{
    int e = blockIdx.z;
    int rows = g_total[e];
    int row0 = blockIdx.x * 128;
    if (row0 >= rows) return;
    int n0 = blockIdx.y * 128;

    extern __shared__ char dyn[];
    uint32_t sbase = smem_to_u32(dyn);
    __shared__ int stok[128];

    int tid = threadIdx.x, lane = tid & 31, wid = tid >> 5;
    if (tid < 128) {
        int r = row0 + tid;
        stok[tid] = (r < rows) ? g_idx[e*CAP + r] : -1;
    }
    __syncthreads();

    const __half* w1e = g_w1h + (size_t)e * NDFF * NC;

    // 1024 16B chunks per stage: arr(2) x row(128) x seg(4)
    auto load_stage = [&](int kt, int stage) {
        int k0 = kt * 32;
        uint32_t sb = sbase + stage * STAGE_B;
#pragma unroll
        for (int i = 0; i < 4; i++) {
            int c = tid + i * 256;
            int arr = c >> 9, t = c & 511, row = t >> 2, seg = t & 3;
            uint32_t dst = sb + arr * TILE_B + (uint32_t)(row * TSTRIDE + seg * 8) * 2;
            if (arr == 0) {
                int tok = stok[row];
                const __half* src = g_xh + ((size_t)(tok < 0 ? 0 : tok) * NC + k0 + seg * 8);
                cp16(dst, src, (tok < 0) ? 0 : 16);
            } else {
                cp16(dst, w1e + ((size_t)(n0 + row) * NC + k0 + seg * 8), 16);
            }
        }
        CP_COMMIT();
    };

    int wm = wid >> 2, wn = wid & 3;
    float acc[4][4][4];
#pragma unroll
    for (int i = 0; i < 4; i++)
#pragma unroll
        for (int j = 0; j < 4; j++)
#pragma unroll
            for (int q = 0; q < 4; q++) acc[i][j][q] = 0.f;

    auto compute_stage = [&](int stage) {
        uint32_t aBase = sbase + stage * STAGE_B;
        uint32_t bBase = aBase + TILE_B;
#pragma unroll
        for (int ks = 0; ks < 32; ks += 16) {
            uint32_t bh[4][2];
            uint32_t nloc = ((lane >> 4) & 1) * 8 + (lane & 7);
            uint32_t kof  = (uint32_t)(ks + ((lane >> 3) & 1) * 8);
#pragma unroll
            for (int jj = 0; jj < 2; jj++) {
                uint32_t bd = bBase + (((uint32_t)(wn * 32 + jj * 16) + nloc) * TSTRIDE + kof) * 2;
                uint32_t r[4];
                ldsm4(r, bd);
                bh[jj*2][0]=r[0]; bh[jj*2][1]=r[1]; bh[jj*2+1][0]=r[2]; bh[jj*2+1][1]=r[3];
            }
            uint32_t arow = (uint32_t)(wm * 64 + (lane & 15));
            uint32_t acol = (uint32_t)(ks + (lane >> 4) * 8);
#pragma unroll
            for (int i = 0; i < 4; i++) {
                uint32_t ah[4];
                ldsm4(ah, aBase + ((arow + i * 16) * TSTRIDE + acol) * 2);
#pragma unroll
                for (int j = 0; j < 4; j++)
                    mma16816(acc[i][j], ah, bh[j]);
            }
        }
    };

    load_stage(0, 0);
    for (int kt = 0; kt < 12; kt++) {
        CP_WAIT0();
        __syncthreads();
        if (kt + 1 < 12) load_stage(kt + 1, (kt + 1) & 1);
        compute_stage(kt & 1);
        __syncthreads();
    }

    // epilogue: +bias, relu^2 -> fp16 H
    const float* b1e = b1 + (size_t)e * NDFF + n0;
    int r_in = lane >> 2, cpair = (lane & 3) * 2;
#pragma unroll
    for (int i = 0; i < 4; i++) {
        int r = row0 + wm * 64 + i * 16 + r_in;
#pragma unroll
        for (int j = 0; j < 4; j++) {
            int col = wn * 32 + j * 8 + cpair;
            float bb0 = b1e[col], bb1 = b1e[col + 1];
            float v00 = fmaxf(acc[i][j][0] + bb0, 0.f); v00 *= v00;
            float v01 = fmaxf(acc[i][j][1] + bb1, 0.f); v01 *= v01;
            float v10 = fmaxf(acc[i][j][2] + bb0, 0.f); v10 *= v10;
            float v11 = fmaxf(acc[i][j][3] + bb1, 0.f); v11 *= v11;
            size_t o0 = ((size_t)e*CAP + r) * NDFF + n0 + col;
            size_t o1 = o0 + (size_t)8 * NDFF;
            __half2 p0; p0.x = __float2half_rn(v00); p0.y = __float2half_rn(v01);
            __half2 p1; p1.x = __float2half_rn(v10); p1.y = __float2half_rn(v11);
            *(__half2*)(g_Hh + o0) = p0;
            *(__half2*)(g_Hh + o1) = p1;
        }
    }
}

// GEMM2: A = H, B = w2T, K=1536. Out -> scatter (acc+b2)*gate.
__global__ __launch_bounds__(256, 2)
void ffn2_mma(const float* __restrict__ b2, float* __restrict__ out)
{
    int e = blockIdx.z;
    int rows = g_total[e];
    int row0 = blockIdx.x * 128;
    if (row0 >= rows) return;
    int n0 = blockIdx.y * 128;

    extern __shared__ char dyn[];
    uint32_t sbase = smem_to_u32(dyn);
    __shared__ int   stok[128];
    __shared__ float sg[128];

    int tid = threadIdx.x, lane = tid & 31, wid = tid >> 5;
    if (tid < 128) {
        int r = row0 + tid;
        stok[tid] = (r < rows) ? g_idx[e*CAP + r] : -1;
        sg[tid]   = (r < rows) ? g_gslot[e*CAP + r] : 0.f;
    }
    __syncthreads();

    const __half* w2e = g_w2h + (size_t)e * NC * NDFF;
    const __half* hG  = g_Hh + (size_t)e * CAP * NDFF;

    auto load_stage = [&](int kt, int stage) {
        int k0 = kt * 32;
        uint32_t sb = sbase + stage * STAGE_B;
#pragma unroll
        for (int i = 0; i < 4; i++) {
            int c = tid + i * 256;
            int arr = c >> 9, t = c & 511, row = t >> 2, seg = t & 3;
            uint32_t dst = sb + arr * TILE_B + (uint32_t)(row * TSTRIDE + seg * 8) * 2;
            if (arr == 0) {
                cp16(dst, hG + ((size_t)(row0 + row) * NDFF + k0 + seg * 8), 16);
            } else {
                cp16(dst, w2e + ((size_t)(n0 + row) * NDFF + k0 + seg * 8), 16);
            }
        }
        CP_COMMIT();
    };

    int wm = wid >> 2, wn = wid & 3;
    float acc[4][4][4];
#pragma unroll
    for (int i = 0; i < 4; i++)
#pragma unroll
        for (int j = 0; j < 4; j++)
#pragma unroll
            for (int q = 0; q < 4; q++) acc[i][j][q] = 0.f;

    auto compute_stage = [&](int stage) {
        uint32_t aBase = sbase + stage * STAGE_B;
        uint32_t bBase = aBase + TILE_B;
#pragma unroll
        for (int ks = 0; ks < 32; ks += 16) {
            uint32_t bh[4][2];
            uint32_t nloc = ((lane >> 4) & 1) * 8 + (lane & 7);
            uint32_t kof  = (uint32_t)(ks + ((lane >> 3) & 1) * 8);
#pragma unroll
            for (int jj = 0; jj < 2; jj++) {
                uint32_t bd = bBase + (((uint32_t)(wn * 32 + jj * 16) + nloc) * TSTRIDE + kof) * 2;
                uint32_t r[4];
                ldsm4(r, bd);
                bh[jj*2][0]=r[0]; bh[jj*2][1]=r[1]; bh[jj*2+1][0]=r[2]; bh[jj*2+1][1]=r[3];
            }
            uint32_t arow = (uint32_t)(wm * 64 + (lane & 15));
            uint32_t acol = (uint32_t)(ks + (lane >> 4) * 8);
#pragma unroll
            for (int i = 0; i < 4; i++) {
                uint32_t ah[4];
                ldsm4(ah, aBase + ((arow + i * 16) * TSTRIDE + acol) * 2);
#pragma unroll
                for (int j = 0; j < 4; j++)
                    mma16816(acc[i][j], ah, bh[j]);
            }
        }
    };

    load_stage(0, 0);
    for (int kt = 0; kt < 48; kt++) {
        CP_WAIT0();
        __syncthreads();
        if (kt + 1 < 48) load_stage(kt + 1, (kt + 1) & 1);
        compute_stage(kt & 1);
        __syncthreads();
    }

    // epilogue: (acc + b2) * gate, scattered float2 stores
    const float* b2e = b2 + (size_t)e * NC + n0;
    int r_in = lane >> 2, cpair = (lane & 3) * 2;
#pragma unroll
    for (int i = 0; i < 4; i++) {
        int rl0 = wm * 64 + i * 16 + r_in;
        int rl1 = rl0 + 8;
#pragma unroll
        for (int j = 0; j < 4; j++) {
            int col = wn * 32 + j * 8 + cpair;
            float bb0 = b2e[col], bb1 = b2e[col + 1];
            if (row0 + rl0 < rows) {
                int tok = stok[rl0]; float g = sg[rl0];
                float2 v = make_float2((acc[i][j][0] + bb0) * g, (acc[i][j][1] + bb1) * g);
                *(float2*)(out + (size_t)tok * NC + n0 + col) = v;
            }
            if (row0 + rl1 < rows) {
                int tok = stok[rl1]; float g = sg[rl1];
                float2 v = make_float2((acc[i][j][2] + bb0) * g, (acc[i][j][3] + bb1) * g);
                *(float2*)(out + (size_t)tok * NC + n0 + col) = v;
            }
        }
    }
}

// ---------------- launch ----------------
extern "C" void kernel_launch(void* const* d_in, const int* in_sizes, int n_in,
                              void* d_out, int out_size)
{
    const float* x  = (const float*)d_in[0];
    const float* noise = (const float*)d_in[1];
    const float* wr = (const float*)d_in[2];
    const float* br = (const float*)d_in[3];
    const float* wn = (const float*)d_in[4];
    const float* bn = (const float*)d_in[5];
    const float* w1 = (const float*)d_in[6];
    const float* b1 = (const float*)d_in[7];
    const float* w2 = (const float*)d_in[8];
    const float* b2 = (const float*)d_in[9];
    float* out = (float*)d_out;

    cudaFuncSetAttribute(ffn1_mma, cudaFuncAttributeMaxDynamicSharedMemorySize, DYN_B);
    cudaFuncSetAttribute(ffn2_mma, cudaFuncAttributeMaxDynamicSharedMemorySize, DYN_B);

    // 1-4: routing + dispatch (x fp16 convert fused into route)
    route_kernel<<<NTOK/8, 256>>>(x, noise, wr, br, wn, bn);
    hist_kernel<<<NCHUNK, CHUNK>>>();
    scan_kernel<<<1, 32>>>();
    scatter_kernel<<<NCHUNK, CHUNK>>>();

    // 5: weight transpose+convert
    transpose_cvt_all<<<dim3(48, 12, 2*NE), dim3(32, 8)>>>(w1, w2);

    // 6: GEMM1  (profiled slot: ncu -s 5 -c 1)
    dim3 g1(CAP/128, NDFF/128, NE);
    ffn1_mma<<<g1, 256, DYN_B>>>(b1);

    // 7: zero output
    int n4 = out_size / 4;
    zero_kernel<<<(n4 + 255)/256, 256>>>((float4*)out, n4);

    // 8: GEMM2
    dim3 g2(CAP/128, NC/128, NE);
    ffn2_mma<<<g2, 256, DYN_B>>>(b2, out);
}

// round 8
// speedup vs baseline: 4.6548x; 1.0128x over previous
#include <cuda_runtime.h>
#include <cuda_fp16.h>
#include <math.h>
#include <stdint.h>

// Problem constants
#define NB 16
#define NT 2048
#define NC 384
#define NE 8
#define NDFF 1536
#define NTOK (NB*NT)          // 32768
#define CAP 8192
#define CHUNK 128
#define NCHUNK (NTOK/CHUNK)   // 256

// ---------------- device scratch ----------------
__device__ int   g_expert[NTOK];
__device__ float g_gate[NTOK];
__device__ int   g_hist[NCHUNK][NE];
__device__ int   g_base[NCHUNK][NE];
__device__ int   g_total[NE];
__device__ int   g_idx[NE*CAP];
__device__ float g_gslot[NE*CAP];

__device__ __half g_xh[(size_t)NTOK*NC];
__device__ __half g_w1h[(size_t)NE*NDFF*NC];   // [E][DFF][C] K-major
__device__ __half g_w2h[(size_t)NE*NC*NDFF];   // [E][C][DFF] K-major
__device__ __half g_Hh[(size_t)NE*CAP*NDFF];

// ---------------- helpers ----------------
__device__ __forceinline__ uint32_t smem_to_u32(const void* p) {
    uint32_t a;
    asm("{ .reg .u64 t; cvta.to.shared.u64 t, %1; cvt.u32.u64 %0, t; }" : "=r"(a) : "l"(p));
    return a;
}
__device__ __forceinline__ void ldsm4(uint32_t* r, uint32_t addr) {
    asm volatile("ldmatrix.sync.aligned.m8n8.x4.shared.b16 {%0,%1,%2,%3}, [%4];"
        : "=r"(r[0]), "=r"(r[1]), "=r"(r[2]), "=r"(r[3]) : "r"(addr));
}
__device__ __forceinline__ void mma16816(float* d, const uint32_t* a, const uint32_t* b) {
    asm volatile("mma.sync.aligned.m16n8k16.row.col.f32.f16.f16.f32 "
        "{%0,%1,%2,%3}, {%4,%5,%6,%7}, {%8,%9}, {%0,%1,%2,%3};"
        : "+f"(d[0]), "+f"(d[1]), "+f"(d[2]), "+f"(d[3])
        : "r"(a[0]), "r"(a[1]), "r"(a[2]), "r"(a[3]), "r"(b[0]), "r"(b[1]));
}
__device__ __forceinline__ void cp16(uint32_t dst, const void* src, int sz) {
    asm volatile("cp.async.cg.shared.global [%0], [%1], 16, %2;"
        :: "r"(dst), "l"(src), "r"(sz) : "memory");
}
#define CP_COMMIT() asm volatile("cp.async.commit_group;" ::: "memory")
#define CP_WAIT0()  asm volatile("cp.async.wait_group 0;" ::: "memory")
#define CP_WAIT1()  asm volatile("cp.async.wait_group 1;" ::: "memory")

// ---------------- zero: out + hist ----------------
__global__ void zero_all(float4* __restrict__ out, int n4)
{
    int i = blockIdx.x * blockDim.x + threadIdx.x;
    if (i < n4) out[i] = make_float4(0.f, 0.f, 0.f, 0.f);
    if (blockIdx.x == 0) {
        int* h = (int*)g_hist;
        for (int k = threadIdx.x; k < NCHUNK*NE; k += blockDim.x) h[k] = 0;
    }
}

// ---------------- fused routing + x-convert + hist  AND  weight transpose ----------------
// blocks [0, 4096): routing, 8 tokens per block (1 warp each)
// blocks [4096, 13312): weight transpose+convert (48*12*16 tiles)
#define RT_ROUTE_BLKS (NTOK/8)                 // 4096
#define RT_TRANS_BLKS (48*12*2*NE)             // 9216
__global__ void route_trans_kernel(const float* __restrict__ x,
                                   const float* __restrict__ noise,
                                   const float* __restrict__ wr, const float* __restrict__ br,
                                   const float* __restrict__ wn, const float* __restrict__ bn,
                                   const float* __restrict__ w1, const float* __restrict__ w2)
{
    int tid = threadIdx.x;
    if (blockIdx.x < RT_ROUTE_BLKS) {
        // ---- routing ----
        int warp = (blockIdx.x * blockDim.x + tid) >> 5;
        int lane = tid & 31;
        const float* xr = x + (size_t)warp * NC;
        float accr[NE], accn[NE];
#pragma unroll
        for (int e = 0; e < NE; e++) { accr[e] = 0.f; accn[e] = 0.f; }
        for (int c = lane; c < NC; c += 32) {
            float xv = xr[c];
            g_xh[(size_t)warp*NC + c] = __float2half_rn(xv);
#pragma unroll
            for (int e = 0; e < NE; e++) {
                accr[e] += xv * wr[c*NE + e];
                accn[e] += xv * wn[c*NE + e];
            }
        }
#pragma unroll
        for (int e = 0; e < NE; e++) {
#pragma unroll
            for (int o = 16; o > 0; o >>= 1) {
                accr[e] += __shfl_xor_sync(0xffffffffu, accr[e], o);
                accn[e] += __shfl_xor_sync(0xffffffffu, accn[e], o);
            }
        }
        if (lane == 0) {
            float v1 = -INFINITY, v2 = -INFINITY;
            int i1 = 0;
#pragma unroll
            for (int e = 0; e < NE; e++) {
                float z  = accn[e] + bn[e];
                float sp = (z > 20.f) ? z : log1pf(expf(z));
                float nv = accr[e] + br[e] + noise[(size_t)warp*NE + e] * sp;
                if (nv > v1) { v2 = v1; v1 = nv; i1 = e; }
                else if (nv > v2) { v2 = nv; }
            }
            g_expert[warp] = i1;
            g_gate[warp]   = 1.f / (1.f + expf(v2 - v1));
            atomicAdd(&g_hist[warp >> 7][i1], 1);
        }
    } else {
        // ---- weight transpose + fp16 convert ----
        __shared__ float t[32][33];
        int f = blockIdx.x - RT_ROUTE_BLKS;
        int xk = f % 48, yk = (f / 48) % 12, z = f / (48*12);
        int tx = tid & 31, ty = tid >> 5;          // 32 x 8
        int R, C, c_blk, r_blk;
        const float* s;
        __half* dh;
        if (z < NE) {
            R = NC; C = NDFF;
            s = w1 + (size_t)z * R * C;
            dh = g_w1h + (size_t)z * R * C;
            c_blk = xk; r_blk = yk;
        } else {
            R = NDFF; C = NC;
            s = w2 + (size_t)(z - NE) * R * C;
            dh = g_w2h + (size_t)(z - NE) * R * C;
            r_blk = xk; c_blk = yk;
        }
        int c0 = c_blk * 32, r0 = r_blk * 32;
#pragma unroll
        for (int i = 0; i < 32; i += 8)
            t[ty + i][tx] = s[(size_t)(r0 + ty + i) * C + c0 + tx];
        __syncthreads();
#pragma unroll
        for (int i = 0; i < 32; i += 8) {
            float v = t[tx][ty + i];
            dh[(size_t)(c0 + ty + i) * R + r0 + tx] = __float2half_rn(v);
        }
    }
}

// ---------------- dispatch ----------------
__global__ void scan_kernel()
{
    int e = threadIdx.x;
    if (e >= NE) return;
    int running = 0;
    for (int ch = 0; ch < NCHUNK; ch++) {
        g_base[ch][e] = running;
        running += g_hist[ch][e];
    }
    g_total[e] = running < CAP ? running : CAP;
}
__global__ void scatter_kernel()
{
    __shared__ int se[CHUNK];
    int tid = threadIdx.x;
    int t = blockIdx.x * CHUNK + tid;
    se[tid] = g_expert[t];
    __syncthreads();
    int e = se[tid];
    int rank = 0;
    for (int j = 0; j < tid; j++) rank += (se[j] == e);
    int pos = g_base[blockIdx.x][e] + rank;
    if (pos < CAP) {
        g_idx[e*CAP + pos]   = t;
        g_gslot[e*CAP + pos] = g_gate[t];
    }
}

// ================= fp16 mma FFN kernels =================
// Tile 128(M) x 128(N), K-tile 32, 8 warps (2M x 4N), warp = 64x32.
// 3-stage cp.async pipeline, one __syncthreads per K-iter.
#define TSTRIDE 40
#define TILE_B  10240
#define STAGE_B (2*TILE_B)       // 20480 (A + B)
#define NSTAGE  3
#define DYN_B   (NSTAGE*STAGE_B) // 61440

// GEMM1: A = gathered x, B = w1T, K=384 (12 iters). Out -> H fp16 after bias/relu^2.
__global__ __launch_bounds__(256, 2)
void ffn1_mma(const float* __restrict__ b1)
{
    int e = blockIdx.z;
    int rows = g_total[e];
    int row0 = blockIdx.x * 128;
    if (row0 >= rows) return;
    int n0 = blockIdx.y * 128;

    extern __shared__ char dyn[];
    uint32_t sbase = smem_to_u32(dyn);
    __shared__ int stok[128];

    int tid = threadIdx.x, lane = tid & 31, wid = tid >> 5;
    if (tid < 128) {
        int r = row0 + tid;
        stok[tid] = (r < rows) ? g_idx[e*CAP + r] : -1;
    }
    __syncthreads();

    const __half* w1e = g_w1h + (size_t)e * NDFF * NC;

    auto load_stage = [&](int kt, int buf) {
        int k0 = kt * 32;
        uint32_t sb = sbase + buf * STAGE_B;
#pragma unroll
        for (int i = 0; i < 4; i++) {
            int c = tid + i * 256;
            int arr = c >> 9, t = c & 511, row = t >> 2, seg = t & 3;
            uint32_t dst = sb + arr * TILE_B + (uint32_t)(row * TSTRIDE + seg * 8) * 2;
            if (arr == 0) {
                int tok = stok[row];
                const __half* src = g_xh + ((size_t)(tok < 0 ? 0 : tok) * NC + k0 + seg * 8);
                cp16(dst, src, (tok < 0) ? 0 : 16);
            } else {
                cp16(dst, w1e + ((size_t)(n0 + row) * NC + k0 + seg * 8), 16);
            }
        }
        CP_COMMIT();
    };

    int wm = wid >> 2, wn = wid & 3;
    float acc[4][4][4];
#pragma unroll
    for (int i = 0; i < 4; i++)
#pragma unroll
        for (int j = 0; j < 4; j++)
#pragma unroll
            for (int q = 0; q < 4; q++) acc[i][j][q] = 0.f;

    auto compute_stage = [&](int buf) {
        uint32_t aBase = sbase + buf * STAGE_B;
        uint32_t bBase = aBase + TILE_B;
#pragma unroll
        for (int ks = 0; ks < 32; ks += 16) {
            uint32_t bh[4][2];
            uint32_t nloc = ((lane >> 4) & 1) * 8 + (lane & 7);
            uint32_t kof  = (uint32_t)(ks + ((lane >> 3) & 1) * 8);
#pragma unroll
            for (int jj = 0; jj < 2; jj++) {
                uint32_t bd = bBase + (((uint32_t)(wn * 32 + jj * 16) + nloc) * TSTRIDE + kof) * 2;
                uint32_t r[4];
                ldsm4(r, bd);
                bh[jj*2][0]=r[0]; bh[jj*2][1]=r[1]; bh[jj*2+1][0]=r[2]; bh[jj*2+1][1]=r[3];
            }
            uint32_t arow = (uint32_t)(wm * 64 + (lane & 15));
            uint32_t acol = (uint32_t)(ks + (lane >> 4) * 8);
#pragma unroll
            for (int i = 0; i < 4; i++) {
                uint32_t ah[4];
                ldsm4(ah, aBase + ((arow + i * 16) * TSTRIDE + acol) * 2);
#pragma unroll
                for (int j = 0; j < 4; j++)
                    mma16816(acc[i][j], ah, bh[j]);
            }
        }
    };

    const int NK = 12;
    load_stage(0, 0);
    load_stage(1, 1);
    for (int kt = 0; kt < NK; kt++) {
        if (kt + 1 == NK) { CP_WAIT0(); } else { CP_WAIT1(); }
        __syncthreads();
        if (kt + 2 < NK) load_stage(kt + 2, (kt + 2) % NSTAGE);
        compute_stage(kt % NSTAGE);
    }

    // epilogue: +bias, relu^2 -> fp16 H
    const float* b1e = b1 + (size_t)e * NDFF + n0;
    int r_in = lane >> 2, cpair = (lane & 3) * 2;
#pragma unroll
    for (int i = 0; i < 4; i++) {
        int r = row0 + wm * 64 + i * 16 + r_in;
#pragma unroll
        for (int j = 0; j < 4; j++) {
            int col = wn * 32 + j * 8 + cpair;
            float bb0 = b1e[col], bb1 = b1e[col + 1];
            float v00 = fmaxf(acc[i][j][0] + bb0, 0.f); v00 *= v00;
            float v01 = fmaxf(acc[i][j][1] + bb1, 0.f); v01 *= v01;
            float v10 = fmaxf(acc[i][j][2] + bb0, 0.f); v10 *= v10;
            float v11 = fmaxf(acc[i][j][3] + bb1, 0.f); v11 *= v11;
            size_t o0 = ((size_t)e*CAP + r) * NDFF + n0 + col;
            size_t o1 = o0 + (size_t)8 * NDFF;
            __half2 p0; p0.x = __float2half_rn(v00); p0.y = __float2half_rn(v01);
            __half2 p1; p1.x = __float2half_rn(v10); p1.y = __float2half_rn(v11);
            *(__half2*)(g_Hh + o0) = p0;
            *(__half2*)(g_Hh + o1) = p1;
        }
    }
}

// GEMM2: A = H, B = w2T, K=1536 (48 iters). Out -> scatter (acc+b2)*gate.
__global__ __launch_bounds__(256, 2)
void ffn2_mma(const float* __restrict__ b2, float* __restrict__ out)
{
    int e = blockIdx.z;
    int rows = g_total[e];
    int row0 = blockIdx.x * 128;
    if (row0 >= rows) return;
    int n0 = blockIdx.y * 128;

    extern __shared__ char dyn[];
    uint32_t sbase = smem_to_u32(dyn);
    __shared__ int   stok[128];
    __shared__ float sg[128];

    int tid = threadIdx.x, lane = tid & 31, wid = tid >> 5;
    if (tid < 128) {
        int r = row0 + tid;
        stok[tid] = (r < rows) ? g_idx[e*CAP + r] : -1;
        sg[tid]   = (r < rows) ? g_gslot[e*CAP + r] : 0.f;
    }
    __syncthreads();

    const __half* w2e = g_w2h + (size_t)e * NC * NDFF;
    const __half* hG  = g_Hh + (size_t)e * CAP * NDFF;

    auto load_stage = [&](int kt, int buf) {
        int k0 = kt * 32;
        uint32_t sb = sbase + buf * STAGE_B;
#pragma unroll
        for (int i = 0; i < 4; i++) {
            int c = tid + i * 256;
            int arr = c >> 9, t = c & 511, row = t >> 2, seg = t & 3;
            uint32_t dst = sb + arr * TILE_B + (uint32_t)(row * TSTRIDE + seg * 8) * 2;
            if (arr == 0) {
                cp16(dst, hG + ((size_t)(row0 + row) * NDFF + k0 + seg * 8), 16);
            } else {
                cp16(dst, w2e + ((size_t)(n0 + row) * NDFF + k0 + seg * 8), 16);
            }
        }
        CP_COMMIT();
    };

    int wm = wid >> 2, wn = wid & 3;
    float acc[4][4][4];
#pragma unroll
    for (int i = 0; i < 4; i++)
#pragma unroll
        for (int j = 0; j < 4; j++)
#pragma unroll
            for (int q = 0; q < 4; q++) acc[i][j][q] = 0.f;

    auto compute_stage = [&](int buf) {
        uint32_t aBase = sbase + buf * STAGE_B;
        uint32_t bBase = aBase + TILE_B;
#pragma unroll
        for (int ks = 0; ks < 32; ks += 16) {
            uint32_t bh[4][2];
            uint32_t nloc = ((lane >> 4) & 1) * 8 + (lane & 7);
            uint32_t kof  = (uint32_t)(ks + ((lane >> 3) & 1) * 8);
#pragma unroll
            for (int jj = 0; jj < 2; jj++) {
                uint32_t bd = bBase + (((uint32_t)(wn * 32 + jj * 16) + nloc) * TSTRIDE + kof) * 2;
                uint32_t r[4];
                ldsm4(r, bd);
                bh[jj*2][0]=r[0]; bh[jj*2][1]=r[1]; bh[jj*2+1][0]=r[2]; bh[jj*2+1][1]=r[3];
            }
            uint32_t arow = (uint32_t)(wm * 64 + (lane & 15));
            uint32_t acol = (uint32_t)(ks + (lane >> 4) * 8);
#pragma unroll
            for (int i = 0; i < 4; i++) {
                uint32_t ah[4];
                ldsm4(ah, aBase + ((arow + i * 16) * TSTRIDE + acol) * 2);
#pragma unroll
                for (int j = 0; j < 4; j++)
                    mma16816(acc[i][j], ah, bh[j]);
            }
        }
    };

    const int NK = 48;
    load_stage(0, 0);
    load_stage(1, 1);
    for (int kt = 0; kt < NK; kt++) {
        if (kt + 1 == NK) { CP_WAIT0(); } else { CP_WAIT1(); }
        __syncthreads();
        if (kt + 2 < NK) load_stage(kt + 2, (kt + 2) % NSTAGE);
        compute_stage(kt % NSTAGE);
    }

    // epilogue: (acc + b2) * gate, scattered float2 stores
    const float* b2e = b2 + (size_t)e * NC + n0;
    int r_in = lane >> 2, cpair = (lane & 3) * 2;
#pragma unroll
    for (int i = 0; i < 4; i++) {
        int rl0 = wm * 64 + i * 16 + r_in;
        int rl1 = rl0 + 8;
#pragma unroll
        for (int j = 0; j < 4; j++) {
            int col = wn * 32 + j * 8 + cpair;
            float bb0 = b2e[col], bb1 = b2e[col + 1];
            if (row0 + rl0 < rows) {
                int tok = stok[rl0]; float g = sg[rl0];
                float2 v = make_float2((acc[i][j][0] + bb0) * g, (acc[i][j][1] + bb1) * g);
                *(float2*)(out + (size_t)tok * NC + n0 + col) = v;
            }
            if (row0 + rl1 < rows) {
                int tok = stok[rl1]; float g = sg[rl1];
                float2 v = make_float2((acc[i][j][2] + bb0) * g, (acc[i][j][3] + bb1) * g);
                *(float2*)(out + (size_t)tok * NC + n0 + col) = v;
            }
        }
    }
}

// ---------------- launch ----------------
extern "C" void kernel_launch(void* const* d_in, const int* in_sizes, int n_in,
                              void* d_out, int out_size)
{
    const float* x  = (const float*)d_in[0];
    const float* noise = (const float*)d_in[1];
    const float* wr = (const float*)d_in[2];
    const float* br = (const float*)d_in[3];
    const float* wn = (const float*)d_in[4];
    const float* bn = (const float*)d_in[5];
    const float* w1 = (const float*)d_in[6];
    const float* b1 = (const float*)d_in[7];
    const float* w2 = (const float*)d_in[8];
    const float* b2 = (const float*)d_in[9];
    float* out = (float*)d_out;

    cudaFuncSetAttribute(ffn1_mma, cudaFuncAttributeMaxDynamicSharedMemorySize, DYN_B);
    cudaFuncSetAttribute(ffn2_mma, cudaFuncAttributeMaxDynamicSharedMemorySize, DYN_B);

    // 1: zero output + histogram
    int n4 = out_size / 4;
    zero_all<<<(n4 + 255)/256, 256>>>((float4*)out, n4);

    // 2: fused routing (+x cvt, +hist) and weight transpose+convert
    route_trans_kernel<<<RT_ROUTE_BLKS + RT_TRANS_BLKS, 256>>>(
        x, noise, wr, br, wn, bn, w1, w2);

    // 3-4: scan + stable scatter
    scan_kernel<<<1, 32>>>();
    scatter_kernel<<<NCHUNK, CHUNK>>>();

    // 5: GEMM1
    dim3 g1(CAP/128, NDFF/128, NE);
    ffn1_mma<<<g1, 256, DYN_B>>>(b1);

    // 6: GEMM2
    dim3 g2(CAP/128, NC/128, NE);
    ffn2_mma<<<g2, 256, DYN_B>>>(b2, out);
}